// round 1
// baseline (speedup 1.0000x reference)
#include <cuda_runtime.h>
#include <math.h>

// Problem constants
#define BDIM   512
#define SDIM   1024
#define BATCH  8
#define NHEADS 8
#define HD     64
#define DFF    2048
#define NTOK   (BATCH * SDIM)   // 8192

// Scratch (device globals; no cudaMalloc allowed)
__device__ float g_q [BATCH * BDIM * SDIM];   // [B, D, S]  (co-major, s contiguous)
__device__ float g_k [BATCH * BDIM * SDIM];
__device__ float g_v [BATCH * BDIM * SDIM];
__device__ float g_av[NTOK * BDIM];           // [B*S, D]
__device__ float g_t1[NTOK * BDIM];
__device__ float g_x1[NTOK * BDIM];
__device__ float g_ff[NTOK * DFF];

// ---------------------------------------------------------------------------
// Conv-as-GEMM: out[b, co, s] = bias[co] + sum_{k,ci} x[b, s+k-pad, ci] * W[co, ci, k]
// out layout: [B, D, S] (s contiguous). 64x64 tile, 256 threads, 4x4 per thread.
// ---------------------------------------------------------------------------
__global__ void conv_kernel(const float* __restrict__ x, const float* __restrict__ W,
                            const float* __restrict__ bias, float* __restrict__ out,
                            int ksize) {
    const int s0 = blockIdx.x * 64;
    const int c0 = blockIdx.y * 64;
    const int b  = blockIdx.z;
    const int pad = (ksize - 1) >> 1;
    const int Kdim = BDIM * ksize;

    __shared__ __align__(16) float As[16][68];  // W tile: As[kk][co_local]
    __shared__ __align__(16) float Bs[16][68];  // x tile: Bs[kk][s_local]

    const int tid = threadIdx.x;
    const int tx = tid & 15, ty = tid >> 4;
    const int lkk = tid & 15, lrow = tid >> 4;

    const float* xb = x + (size_t)b * SDIM * BDIM;

    float acc[4][4] = {{0.f,0.f,0.f,0.f},{0.f,0.f,0.f,0.f},{0.f,0.f,0.f,0.f},{0.f,0.f,0.f,0.f}};

    for (int kb = 0; kb < Kdim; kb += 16) {
        const int j  = kb + lkk;
        const int kt = j / BDIM;          // kernel tap (constant within the 16-chunk)
        const int ci = j - kt * BDIM;

        // W tile (64 co rows)
        #pragma unroll
        for (int r = 0; r < 4; r++) {
            int co = c0 + lrow + 16 * r;
            As[lkk][lrow + 16 * r] = W[(size_t)co * Kdim + ci * ksize + kt];
        }
        // x (im2col) tile
        const int sbase = s0 + kt - pad;
        #pragma unroll
        for (int r = 0; r < 4; r++) {
            int sl = lrow + 16 * r;
            int ssrc = sbase + sl;
            float v = 0.f;
            if (ssrc >= 0 && ssrc < SDIM) v = xb[(size_t)ssrc * BDIM + ci];
            Bs[lkk][sl] = v;
        }
        __syncthreads();

        #pragma unroll
        for (int kk = 0; kk < 16; kk++) {
            float4 a  = *(const float4*)&As[kk][ty * 4];
            float4 bb = *(const float4*)&Bs[kk][tx * 4];
            float av0[4] = {a.x, a.y, a.z, a.w};
            float bv0[4] = {bb.x, bb.y, bb.z, bb.w};
            #pragma unroll
            for (int i = 0; i < 4; i++)
                #pragma unroll
                for (int jj = 0; jj < 4; jj++)
                    acc[i][jj] += av0[i] * bv0[jj];
        }
        __syncthreads();
    }

    #pragma unroll
    for (int i = 0; i < 4; i++) {
        int co = c0 + ty * 4 + i;
        float bv = bias[co];
        float4 o;
        o.x = acc[i][0] + bv; o.y = acc[i][1] + bv;
        o.z = acc[i][2] + bv; o.w = acc[i][3] + bv;
        *(float4*)&out[((size_t)(b * BDIM + co)) * SDIM + s0 + tx * 4] = o;
    }
}

// ---------------------------------------------------------------------------
// Flash-style attention. q,k,v in [B, H, hd, S] == [B, D, S]. One block per
// (b, h, 64-query tile). Online softmax, scores scaled by 1/hd folded into Q.
// Output written to g_av in [B*S, D] layout (col = h*64 + d).
// ---------------------------------------------------------------------------
__global__ void attn_kernel(const float* __restrict__ q, const float* __restrict__ k,
                            const float* __restrict__ v, float* __restrict__ av) {
    const int s0 = blockIdx.x * 64;
    const int h  = blockIdx.y;
    const int b  = blockIdx.z;
    const size_t base = (size_t)(b * NHEADS + h) * HD * SDIM;
    const float* qb = q + base;
    const float* kb = k + base;
    const float* vb = v + base;

    __shared__ __align__(16) float Qs[64][68];  // [d][s]
    __shared__ __align__(16) float Ks[64][68];  // [d][t]
    __shared__ float Vs[64][65];                // [d][t]
    __shared__ float Ps[64][65];                // [s][t]

    const int tid = threadIdx.x;
    const int tx = tid & 15, ty = tid >> 4;
    const int tl = tid & 63, dq = tid >> 6;

    // Load Q tile with 1/hd scaling
    #pragma unroll
    for (int r = 0; r < 16; r++) {
        int d = dq + 4 * r;
        Qs[d][tl] = qb[(size_t)d * SDIM + s0 + tl] * (1.0f / 64.0f);
    }

    float m[4], l[4], o[4][4];
    #pragma unroll
    for (int i = 0; i < 4; i++) {
        m[i] = -1e30f; l[i] = 0.f;
        #pragma unroll
        for (int j = 0; j < 4; j++) o[i][j] = 0.f;
    }

    for (int t0 = 0; t0 < SDIM; t0 += 64) {
        __syncthreads();   // previous PV done; safe to overwrite Ks/Vs
        #pragma unroll
        for (int r = 0; r < 16; r++) {
            int d = dq + 4 * r;
            Ks[d][tl] = kb[(size_t)d * SDIM + t0 + tl];
            Vs[d][tl] = vb[(size_t)d * SDIM + t0 + tl];
        }
        __syncthreads();

        // scores[s][t] = sum_d Q[d][s] * K[d][t]
        float sc[4][4] = {{0.f,0.f,0.f,0.f},{0.f,0.f,0.f,0.f},{0.f,0.f,0.f,0.f},{0.f,0.f,0.f,0.f}};
        #pragma unroll
        for (int d = 0; d < 64; d++) {
            float4 a  = *(const float4*)&Qs[d][ty * 4];
            float4 bb = *(const float4*)&Ks[d][tx * 4];
            float av0[4] = {a.x, a.y, a.z, a.w};
            float bv0[4] = {bb.x, bb.y, bb.z, bb.w};
            #pragma unroll
            for (int i = 0; i < 4; i++)
                #pragma unroll
                for (int j = 0; j < 4; j++)
                    sc[i][j] += av0[i] * bv0[j];
        }

        // online softmax update (row reductions across the 16 tx lanes)
        #pragma unroll
        for (int i = 0; i < 4; i++) {
            float rm = fmaxf(fmaxf(sc[i][0], sc[i][1]), fmaxf(sc[i][2], sc[i][3]));
            #pragma unroll
            for (int off = 1; off < 16; off <<= 1)
                rm = fmaxf(rm, __shfl_xor_sync(0xffffffffu, rm, off));
            float mn = fmaxf(m[i], rm);
            float corr = __expf(m[i] - mn);
            float rs = 0.f;
            #pragma unroll
            for (int j = 0; j < 4; j++) {
                float p = __expf(sc[i][j] - mn);
                Ps[ty * 4 + i][tx * 4 + j] = p;
                rs += p;
            }
            #pragma unroll
            for (int off = 1; off < 16; off <<= 1)
                rs += __shfl_xor_sync(0xffffffffu, rs, off);
            l[i] = l[i] * corr + rs;
            m[i] = mn;
            #pragma unroll
            for (int j = 0; j < 4; j++) o[i][j] *= corr;
        }
        __syncthreads();   // Ps visible to all

        // O[s][d] += sum_t P[s][t] * V[d][t]
        #pragma unroll 4
        for (int t = 0; t < 64; t++) {
            float a0 = Ps[ty * 4 + 0][t];
            float a1 = Ps[ty * 4 + 1][t];
            float a2 = Ps[ty * 4 + 2][t];
            float a3 = Ps[ty * 4 + 3][t];
            float b0 = Vs[tx * 4 + 0][t];
            float b1 = Vs[tx * 4 + 1][t];
            float b2 = Vs[tx * 4 + 2][t];
            float b3 = Vs[tx * 4 + 3][t];
            o[0][0] += a0 * b0; o[0][1] += a0 * b1; o[0][2] += a0 * b2; o[0][3] += a0 * b3;
            o[1][0] += a1 * b0; o[1][1] += a1 * b1; o[1][2] += a1 * b2; o[1][3] += a1 * b3;
            o[2][0] += a2 * b0; o[2][1] += a2 * b1; o[2][2] += a2 * b2; o[2][3] += a2 * b3;
            o[3][0] += a3 * b0; o[3][1] += a3 * b1; o[3][2] += a3 * b2; o[3][3] += a3 * b3;
        }
    }

    #pragma unroll
    for (int i = 0; i < 4; i++) {
        int s = s0 + ty * 4 + i;
        float inv = 1.0f / l[i];
        float4 ov;
        ov.x = o[i][0] * inv; ov.y = o[i][1] * inv;
        ov.z = o[i][2] * inv; ov.w = o[i][3] * inv;
        *(float4*)&av[((size_t)(b * SDIM + s)) * BDIM + h * HD + tx * 4] = ov;
    }
}

// ---------------------------------------------------------------------------
// GEMM: out[n, m] = A[n, :] . W[m, :] + bias[m]  (+ epilogue per MODE)
// MODE 0: + res[n,m]           (Wo proj + residual src)
// MODE 1: relu                 (FF first layer)
// MODE 2: + res[n,m]           (FF second layer + residual x1)
// ---------------------------------------------------------------------------
template <int MODE>
__global__ void gemm_kernel(const float* __restrict__ A, const float* __restrict__ W,
                            const float* __restrict__ bias, const float* __restrict__ res,
                            float* __restrict__ out, int M, int K) {
    const int n0 = blockIdx.x * 64;
    const int m0 = blockIdx.y * 64;

    __shared__ __align__(16) float As[16][68];
    __shared__ __align__(16) float Ws[16][68];

    const int tid = threadIdx.x;
    const int tx = tid & 15, ty = tid >> 4;
    const int lkk = tid & 15, lrow = tid >> 4;

    float acc[4][4] = {{0.f,0.f,0.f,0.f},{0.f,0.f,0.f,0.f},{0.f,0.f,0.f,0.f},{0.f,0.f,0.f,0.f}};

    for (int kb = 0; kb < K; kb += 16) {
        #pragma unroll
        for (int r = 0; r < 4; r++) {
            As[lkk][lrow + 16 * r] = A[(size_t)(n0 + lrow + 16 * r) * K + kb + lkk];
            Ws[lkk][lrow + 16 * r] = W[(size_t)(m0 + lrow + 16 * r) * K + kb + lkk];
        }
        __syncthreads();
        #pragma unroll
        for (int kk = 0; kk < 16; kk++) {
            float4 a  = *(const float4*)&As[kk][ty * 4];
            float4 bb = *(const float4*)&Ws[kk][tx * 4];
            float av0[4] = {a.x, a.y, a.z, a.w};
            float bv0[4] = {bb.x, bb.y, bb.z, bb.w};
            #pragma unroll
            for (int i = 0; i < 4; i++)
                #pragma unroll
                for (int j = 0; j < 4; j++)
                    acc[i][j] += av0[i] * bv0[j];
        }
        __syncthreads();
    }

    #pragma unroll
    for (int i = 0; i < 4; i++) {
        int n = n0 + ty * 4 + i;
        float vals[4];
        #pragma unroll
        for (int j = 0; j < 4; j++) {
            int mcol = m0 + tx * 4 + j;
            float vv = acc[i][j] + bias[mcol];
            if (MODE == 1) vv = fmaxf(vv, 0.f);
            if (MODE == 0 || MODE == 2) vv += res[(size_t)n * M + mcol];
            vals[j] = vv;
        }
        float4 o; o.x = vals[0]; o.y = vals[1]; o.z = vals[2]; o.w = vals[3];
        *(float4*)&out[(size_t)n * M + m0 + tx * 4] = o;
    }
}

// ---------------------------------------------------------------------------
// LayerNorm over last dim (512). One block per row, 256 threads.
// ---------------------------------------------------------------------------
__global__ void ln_kernel(const float* __restrict__ in, const float* __restrict__ g,
                          const float* __restrict__ beta, float* __restrict__ out) {
    const int row = blockIdx.x;
    const float* x = in + (size_t)row * BDIM;
    const int tid = threadIdx.x;
    const int wid = tid >> 5, lane = tid & 31;

    float v0 = x[tid], v1 = x[tid + 256];

    __shared__ float red[8];

    float s = v0 + v1;
    #pragma unroll
    for (int off = 16; off > 0; off >>= 1)
        s += __shfl_xor_sync(0xffffffffu, s, off);
    if (lane == 0) red[wid] = s;
    __syncthreads();
    float tot = 0.f;
    #pragma unroll
    for (int i = 0; i < 8; i++) tot += red[i];
    float mu = tot * (1.0f / 512.0f);
    __syncthreads();

    float d0 = v0 - mu, d1 = v1 - mu;
    float sq = d0 * d0 + d1 * d1;
    #pragma unroll
    for (int off = 16; off > 0; off >>= 1)
        sq += __shfl_xor_sync(0xffffffffu, sq, off);
    if (lane == 0) red[wid] = sq;
    __syncthreads();
    float tot2 = 0.f;
    #pragma unroll
    for (int i = 0; i < 8; i++) tot2 += red[i];
    float rstd = rsqrtf(tot2 * (1.0f / 512.0f) + 1e-5f);

    out[(size_t)row * BDIM + tid]       = d0 * rstd * g[tid]       + beta[tid];
    out[(size_t)row * BDIM + tid + 256] = d1 * rstd * g[tid + 256] + beta[tid + 256];
}

// ---------------------------------------------------------------------------
extern "C" void kernel_launch(void* const* d_in, const int* in_sizes, int n_in,
                              void* d_out, int out_size) {
    const float* src = (const float*)d_in[0];
    const float* Wq  = (const float*)d_in[1];
    const float* bq  = (const float*)d_in[2];
    const float* Wk  = (const float*)d_in[3];
    const float* bk  = (const float*)d_in[4];
    const float* Wv  = (const float*)d_in[5];
    const float* bv  = (const float*)d_in[6];
    const float* Wo  = (const float*)d_in[7];
    const float* bo  = (const float*)d_in[8];
    const float* W1  = (const float*)d_in[9];
    const float* b1  = (const float*)d_in[10];
    const float* W2  = (const float*)d_in[11];
    const float* b2  = (const float*)d_in[12];
    const float* g1  = (const float*)d_in[13];
    const float* be1 = (const float*)d_in[14];
    const float* g2  = (const float*)d_in[15];
    const float* be2 = (const float*)d_in[16];
    float* out = (float*)d_out;

    float *q, *k, *v, *av, *t1, *x1, *ff;
    cudaGetSymbolAddress((void**)&q,  g_q);
    cudaGetSymbolAddress((void**)&k,  g_k);
    cudaGetSymbolAddress((void**)&v,  g_v);
    cudaGetSymbolAddress((void**)&av, g_av);
    cudaGetSymbolAddress((void**)&t1, g_t1);
    cudaGetSymbolAddress((void**)&x1, g_x1);
    cudaGetSymbolAddress((void**)&ff, g_ff);

    dim3 cgrid(SDIM / 64, BDIM / 64, BATCH);
    conv_kernel<<<cgrid, 256>>>(src, Wq, bq, q, 3);
    conv_kernel<<<cgrid, 256>>>(src, Wk, bk, k, 3);
    conv_kernel<<<cgrid, 256>>>(src, Wv, bv, v, 1);

    attn_kernel<<<dim3(SDIM / 64, NHEADS, BATCH), 256>>>(q, k, v, av);

    gemm_kernel<0><<<dim3(NTOK / 64, BDIM / 64), 256>>>(av, Wo, bo, src, t1, BDIM, BDIM);
    ln_kernel<<<NTOK, 256>>>(t1, g1, be1, x1);

    gemm_kernel<1><<<dim3(NTOK / 64, DFF / 64), 256>>>(x1, W1, b1, nullptr, ff, DFF, BDIM);
    gemm_kernel<2><<<dim3(NTOK / 64, BDIM / 64), 256>>>(ff, W2, b2, x1, t1, BDIM, DFF);
    ln_kernel<<<NTOK, 256>>>(t1, g2, be2, out);
}

// round 2
// speedup vs baseline: 1.8037x; 1.8037x over previous
#include <cuda_runtime.h>
#include <math.h>
#include <stdint.h>

// Problem constants
#define BDIM   512
#define SDIM   1024
#define BATCH  8
#define NHEADS 8
#define HD     64
#define DFF    2048
#define NTOK   (BATCH * SDIM)   // 8192

// Scratch (device globals; no cudaMalloc allowed)
__device__ float g_q [BATCH * BDIM * SDIM];   // [B, D, S]
__device__ float g_k [BATCH * BDIM * SDIM];
__device__ float g_v [BATCH * BDIM * SDIM];
__device__ float g_av[NTOK * BDIM];           // [B*S, D]
__device__ float g_t1[NTOK * BDIM];
__device__ float g_x1[NTOK * BDIM];
__device__ float g_ff[NTOK * DFF];
__device__ float g_wt[2 * 3 * BDIM * BDIM];   // transposed Wq/Wk: [mat][tap][co][ci]

// ---------------------------------------------------------------------------
// helpers: tf32 convert + mma
// ---------------------------------------------------------------------------
__device__ __forceinline__ uint32_t f2tf(float f) {
    uint32_t r;
    asm("cvt.rna.tf32.f32 %0, %1;" : "=r"(r) : "f"(f));
    return r;
}

__device__ __forceinline__ void mma_tf32(float c[4], const uint32_t a[4], const uint32_t b[2]) {
    asm volatile(
        "mma.sync.aligned.m16n8k8.row.col.f32.tf32.tf32.f32 "
        "{%0,%1,%2,%3}, {%4,%5,%6,%7}, {%8,%9}, {%0,%1,%2,%3};"
        : "+f"(c[0]), "+f"(c[1]), "+f"(c[2]), "+f"(c[3])
        : "r"(a[0]), "r"(a[1]), "r"(a[2]), "r"(a[3]), "r"(b[0]), "r"(b[1]));
}

// ---------------------------------------------------------------------------
// Weight transpose for conv: dst[mat][tap][co][ci] = Wsrc[co][ci*3 + tap]
// ---------------------------------------------------------------------------
__global__ void wtrans_kernel(const float* __restrict__ Wq, const float* __restrict__ Wk,
                              float* __restrict__ dst) {
    int e = blockIdx.x * 256 + threadIdx.x;
    if (e >= 2 * 3 * BDIM * BDIM) return;
    int m  = (e >= 3 * BDIM * BDIM);
    int e2 = e - m * 3 * BDIM * BDIM;
    int t  = e2 >> 18;
    int co = (e2 >> 9) & 511;
    int ci = e2 & 511;
    const float* src = m ? Wk : Wq;
    dst[e] = src[(size_t)co * 1536 + ci * 3 + t];
}

// ---------------------------------------------------------------------------
// Conv as tap-accumulated tf32 tensor-core GEMM.
// A = src [NTOK, 512] row-major; Wt slice [co][ci] contiguous per tap.
// out written in [B, D, S] layout for attention.
// Block tile 128(tokens) x 64(co), 8 warps (32x32 warp tile), KT=32.
// ---------------------------------------------------------------------------
__global__ __launch_bounds__(256) void conv_mma(const float* __restrict__ A,
                                                const float* __restrict__ Wt,
                                                const float* __restrict__ bias,
                                                float* __restrict__ out, int taps) {
    const int n0 = blockIdx.x * 128;
    const int c0 = blockIdx.y * 64;

    __shared__ uint32_t As[128][36];
    __shared__ uint32_t Ws[64][36];

    const int tid  = threadIdx.x;
    const int lane = tid & 31;
    const int warp = tid >> 5;
    const int wi = (warp >> 1) * 32;
    const int wj = (warp & 1) * 32;
    const int lq = lane >> 2;   // 0..7
    const int lr = lane & 3;    // 0..3

    float acc[2][4][4];
    #pragma unroll
    for (int mi = 0; mi < 2; mi++)
        #pragma unroll
        for (int ni = 0; ni < 4; ni++)
            #pragma unroll
            for (int c = 0; c < 4; c++) acc[mi][ni][c] = 0.f;

    for (int tap = 0; tap < taps; tap++) {
        const float* Wsl = Wt + (size_t)tap * BDIM * BDIM;
        const int roff = tap - (taps >> 1);   // taps=3: -1,0,1 ; taps=1: 0

        for (int kb = 0; kb < BDIM; kb += 32) {
            // A tile: 128x32 (row-shifted by roff, zero at batch edges)
            #pragma unroll
            for (int r = 0; r < 4; r++) {
                int v = tid + 256 * r;
                int row = v >> 3, kc = (v & 7) * 4;
                int n = n0 + row;
                int s = (n & 1023) + roff;
                float4 val = make_float4(0.f, 0.f, 0.f, 0.f);
                if ((unsigned)s < 1024u)
                    val = *(const float4*)&A[((size_t)(n & ~1023) + s) * BDIM + kb + kc];
                As[row][kc + 0] = f2tf(val.x);
                As[row][kc + 1] = f2tf(val.y);
                As[row][kc + 2] = f2tf(val.z);
                As[row][kc + 3] = f2tf(val.w);
            }
            // W tile: 64x32
            #pragma unroll
            for (int r = 0; r < 2; r++) {
                int v = tid + 256 * r;
                int row = v >> 3, kc = (v & 7) * 4;
                float4 val = *(const float4*)&Wsl[(size_t)(c0 + row) * BDIM + kb + kc];
                Ws[row][kc + 0] = f2tf(val.x);
                Ws[row][kc + 1] = f2tf(val.y);
                Ws[row][kc + 2] = f2tf(val.z);
                Ws[row][kc + 3] = f2tf(val.w);
            }
            __syncthreads();

            #pragma unroll
            for (int ks = 0; ks < 4; ks++) {
                const int k8 = ks * 8 + lr;
                uint32_t a[2][4], b[4][2];
                #pragma unroll
                for (int mi = 0; mi < 2; mi++) {
                    int rb = wi + mi * 16 + lq;
                    a[mi][0] = As[rb][k8];
                    a[mi][1] = As[rb + 8][k8];
                    a[mi][2] = As[rb][k8 + 4];
                    a[mi][3] = As[rb + 8][k8 + 4];
                }
                #pragma unroll
                for (int ni = 0; ni < 4; ni++) {
                    int jr = wj + ni * 8 + lq;
                    b[ni][0] = Ws[jr][k8];
                    b[ni][1] = Ws[jr][k8 + 4];
                }
                #pragma unroll
                for (int mi = 0; mi < 2; mi++)
                    #pragma unroll
                    for (int ni = 0; ni < 4; ni++)
                        mma_tf32(acc[mi][ni], a[mi], b[ni]);
            }
            __syncthreads();
        }
    }

    // Epilogue: scatter to [B, D, S]
    const int bidx = n0 >> 10;
    const int sbase = (n0 & 1023) + wi;
    #pragma unroll
    for (int mi = 0; mi < 2; mi++) {
        #pragma unroll
        for (int ni = 0; ni < 4; ni++) {
            int co = c0 + wj + ni * 8 + 2 * lr;
            float bv0 = bias[co], bv1 = bias[co + 1];
            #pragma unroll
            for (int h = 0; h < 2; h++) {
                int s = sbase + mi * 16 + lq + h * 8;
                out[((size_t)(bidx * BDIM + co)) * SDIM + s]     = acc[mi][ni][2 * h]     + bv0;
                out[((size_t)(bidx * BDIM + co + 1)) * SDIM + s] = acc[mi][ni][2 * h + 1] + bv1;
            }
        }
    }
}

// ---------------------------------------------------------------------------
// Generic tf32 GEMM: out[n,m] = A[n,:].W[m,:] + bias[m] (+epilogue)
// MODE 0: +res  | MODE 1: relu | MODE 2: +res
// Block 128x64, 8 warps (32x32), KT=32.
// ---------------------------------------------------------------------------
template <int MODE>
__global__ __launch_bounds__(256) void gemm_mma(const float* __restrict__ A,
                                                const float* __restrict__ W,
                                                const float* __restrict__ bias,
                                                const float* __restrict__ res,
                                                float* __restrict__ out, int M, int K) {
    const int n0 = blockIdx.x * 128;
    const int m0 = blockIdx.y * 64;

    __shared__ uint32_t As[128][36];
    __shared__ uint32_t Ws[64][36];

    const int tid  = threadIdx.x;
    const int lane = tid & 31;
    const int warp = tid >> 5;
    const int wi = (warp >> 1) * 32;
    const int wj = (warp & 1) * 32;
    const int lq = lane >> 2;
    const int lr = lane & 3;

    float acc[2][4][4];
    #pragma unroll
    for (int mi = 0; mi < 2; mi++)
        #pragma unroll
        for (int ni = 0; ni < 4; ni++)
            #pragma unroll
            for (int c = 0; c < 4; c++) acc[mi][ni][c] = 0.f;

    for (int kb = 0; kb < K; kb += 32) {
        #pragma unroll
        for (int r = 0; r < 4; r++) {
            int v = tid + 256 * r;
            int row = v >> 3, kc = (v & 7) * 4;
            float4 val = *(const float4*)&A[(size_t)(n0 + row) * K + kb + kc];
            As[row][kc + 0] = f2tf(val.x);
            As[row][kc + 1] = f2tf(val.y);
            As[row][kc + 2] = f2tf(val.z);
            As[row][kc + 3] = f2tf(val.w);
        }
        #pragma unroll
        for (int r = 0; r < 2; r++) {
            int v = tid + 256 * r;
            int row = v >> 3, kc = (v & 7) * 4;
            float4 val = *(const float4*)&W[(size_t)(m0 + row) * K + kb + kc];
            Ws[row][kc + 0] = f2tf(val.x);
            Ws[row][kc + 1] = f2tf(val.y);
            Ws[row][kc + 2] = f2tf(val.z);
            Ws[row][kc + 3] = f2tf(val.w);
        }
        __syncthreads();

        #pragma unroll
        for (int ks = 0; ks < 4; ks++) {
            const int k8 = ks * 8 + lr;
            uint32_t a[2][4], b[4][2];
            #pragma unroll
            for (int mi = 0; mi < 2; mi++) {
                int rb = wi + mi * 16 + lq;
                a[mi][0] = As[rb][k8];
                a[mi][1] = As[rb + 8][k8];
                a[mi][2] = As[rb][k8 + 4];
                a[mi][3] = As[rb + 8][k8 + 4];
            }
            #pragma unroll
            for (int ni = 0; ni < 4; ni++) {
                int jr = wj + ni * 8 + lq;
                b[ni][0] = Ws[jr][k8];
                b[ni][1] = Ws[jr][k8 + 4];
            }
            #pragma unroll
            for (int mi = 0; mi < 2; mi++)
                #pragma unroll
                for (int ni = 0; ni < 4; ni++)
                    mma_tf32(acc[mi][ni], a[mi], b[ni]);
        }
        __syncthreads();
    }

    #pragma unroll
    for (int mi = 0; mi < 2; mi++) {
        #pragma unroll
        for (int ni = 0; ni < 4; ni++) {
            int col = m0 + wj + ni * 8 + 2 * lr;
            float bv0 = bias[col], bv1 = bias[col + 1];
            #pragma unroll
            for (int h = 0; h < 2; h++) {
                int n = n0 + wi + mi * 16 + lq + h * 8;
                float x0 = acc[mi][ni][2 * h] + bv0;
                float x1 = acc[mi][ni][2 * h + 1] + bv1;
                if (MODE == 1) { x0 = fmaxf(x0, 0.f); x1 = fmaxf(x1, 0.f); }
                if (MODE == 0 || MODE == 2) {
                    x0 += res[(size_t)n * M + col];
                    x1 += res[(size_t)n * M + col + 1];
                }
                float2 o2 = make_float2(x0, x1);
                *(float2*)&out[(size_t)n * M + col] = o2;
            }
        }
    }
}

// ---------------------------------------------------------------------------
// Flash-style attention (unchanged from R1). q,k,v in [B, H, hd, S].
// ---------------------------------------------------------------------------
__global__ void attn_kernel(const float* __restrict__ q, const float* __restrict__ k,
                            const float* __restrict__ v, float* __restrict__ av) {
    const int s0 = blockIdx.x * 64;
    const int h  = blockIdx.y;
    const int b  = blockIdx.z;
    const size_t base = (size_t)(b * NHEADS + h) * HD * SDIM;
    const float* qb = q + base;
    const float* kb = k + base;
    const float* vb = v + base;

    __shared__ __align__(16) float Qs[64][68];
    __shared__ __align__(16) float Ks[64][68];
    __shared__ float Vs[64][65];
    __shared__ float Ps[64][65];

    const int tid = threadIdx.x;
    const int tx = tid & 15, ty = tid >> 4;
    const int tl = tid & 63, dq = tid >> 6;

    #pragma unroll
    for (int r = 0; r < 16; r++) {
        int d = dq + 4 * r;
        Qs[d][tl] = qb[(size_t)d * SDIM + s0 + tl] * (1.0f / 64.0f);
    }

    float m[4], l[4], o[4][4];
    #pragma unroll
    for (int i = 0; i < 4; i++) {
        m[i] = -1e30f; l[i] = 0.f;
        #pragma unroll
        for (int j = 0; j < 4; j++) o[i][j] = 0.f;
    }

    for (int t0 = 0; t0 < SDIM; t0 += 64) {
        __syncthreads();
        #pragma unroll
        for (int r = 0; r < 16; r++) {
            int d = dq + 4 * r;
            Ks[d][tl] = kb[(size_t)d * SDIM + t0 + tl];
            Vs[d][tl] = vb[(size_t)d * SDIM + t0 + tl];
        }
        __syncthreads();

        float sc[4][4] = {{0.f,0.f,0.f,0.f},{0.f,0.f,0.f,0.f},{0.f,0.f,0.f,0.f},{0.f,0.f,0.f,0.f}};
        #pragma unroll
        for (int d = 0; d < 64; d++) {
            float4 a  = *(const float4*)&Qs[d][ty * 4];
            float4 bb = *(const float4*)&Ks[d][tx * 4];
            float av0[4] = {a.x, a.y, a.z, a.w};
            float bv0[4] = {bb.x, bb.y, bb.z, bb.w};
            #pragma unroll
            for (int i = 0; i < 4; i++)
                #pragma unroll
                for (int j = 0; j < 4; j++)
                    sc[i][j] += av0[i] * bv0[j];
        }

        #pragma unroll
        for (int i = 0; i < 4; i++) {
            float rm = fmaxf(fmaxf(sc[i][0], sc[i][1]), fmaxf(sc[i][2], sc[i][3]));
            #pragma unroll
            for (int off = 1; off < 16; off <<= 1)
                rm = fmaxf(rm, __shfl_xor_sync(0xffffffffu, rm, off));
            float mn = fmaxf(m[i], rm);
            float corr = __expf(m[i] - mn);
            float rs = 0.f;
            #pragma unroll
            for (int j = 0; j < 4; j++) {
                float p = __expf(sc[i][j] - mn);
                Ps[ty * 4 + i][tx * 4 + j] = p;
                rs += p;
            }
            #pragma unroll
            for (int off = 1; off < 16; off <<= 1)
                rs += __shfl_xor_sync(0xffffffffu, rs, off);
            l[i] = l[i] * corr + rs;
            m[i] = mn;
            #pragma unroll
            for (int j = 0; j < 4; j++) o[i][j] *= corr;
        }
        __syncthreads();

        #pragma unroll 4
        for (int t = 0; t < 64; t++) {
            float a0 = Ps[ty * 4 + 0][t];
            float a1 = Ps[ty * 4 + 1][t];
            float a2 = Ps[ty * 4 + 2][t];
            float a3 = Ps[ty * 4 + 3][t];
            float b0 = Vs[tx * 4 + 0][t];
            float b1 = Vs[tx * 4 + 1][t];
            float b2 = Vs[tx * 4 + 2][t];
            float b3 = Vs[tx * 4 + 3][t];
            o[0][0] += a0 * b0; o[0][1] += a0 * b1; o[0][2] += a0 * b2; o[0][3] += a0 * b3;
            o[1][0] += a1 * b0; o[1][1] += a1 * b1; o[1][2] += a1 * b2; o[1][3] += a1 * b3;
            o[2][0] += a2 * b0; o[2][1] += a2 * b1; o[2][2] += a2 * b2; o[2][3] += a2 * b3;
            o[3][0] += a3 * b0; o[3][1] += a3 * b1; o[3][2] += a3 * b2; o[3][3] += a3 * b3;
        }
    }

    #pragma unroll
    for (int i = 0; i < 4; i++) {
        int s = s0 + ty * 4 + i;
        float inv = 1.0f / l[i];
        float4 ov;
        ov.x = o[i][0] * inv; ov.y = o[i][1] * inv;
        ov.z = o[i][2] * inv; ov.w = o[i][3] * inv;
        *(float4*)&av[((size_t)(b * SDIM + s)) * BDIM + h * HD + tx * 4] = ov;
    }
}

// ---------------------------------------------------------------------------
// LayerNorm over last dim (512). One block per row, 256 threads.
// ---------------------------------------------------------------------------
__global__ void ln_kernel(const float* __restrict__ in, const float* __restrict__ g,
                          const float* __restrict__ beta, float* __restrict__ out) {
    const int row = blockIdx.x;
    const float* x = in + (size_t)row * BDIM;
    const int tid = threadIdx.x;
    const int wid = tid >> 5, lane = tid & 31;

    float v0 = x[tid], v1 = x[tid + 256];

    __shared__ float red[8];

    float s = v0 + v1;
    #pragma unroll
    for (int off = 16; off > 0; off >>= 1)
        s += __shfl_xor_sync(0xffffffffu, s, off);
    if (lane == 0) red[wid] = s;
    __syncthreads();
    float tot = 0.f;
    #pragma unroll
    for (int i = 0; i < 8; i++) tot += red[i];
    float mu = tot * (1.0f / 512.0f);
    __syncthreads();

    float d0 = v0 - mu, d1 = v1 - mu;
    float sq = d0 * d0 + d1 * d1;
    #pragma unroll
    for (int off = 16; off > 0; off >>= 1)
        sq += __shfl_xor_sync(0xffffffffu, sq, off);
    if (lane == 0) red[wid] = sq;
    __syncthreads();
    float tot2 = 0.f;
    #pragma unroll
    for (int i = 0; i < 8; i++) tot2 += red[i];
    float rstd = rsqrtf(tot2 * (1.0f / 512.0f) + 1e-5f);

    out[(size_t)row * BDIM + tid]       = d0 * rstd * g[tid]       + beta[tid];
    out[(size_t)row * BDIM + tid + 256] = d1 * rstd * g[tid + 256] + beta[tid + 256];
}

// ---------------------------------------------------------------------------
extern "C" void kernel_launch(void* const* d_in, const int* in_sizes, int n_in,
                              void* d_out, int out_size) {
    const float* src = (const float*)d_in[0];
    const float* Wq  = (const float*)d_in[1];
    const float* bq  = (const float*)d_in[2];
    const float* Wk  = (const float*)d_in[3];
    const float* bk  = (const float*)d_in[4];
    const float* Wv  = (const float*)d_in[5];
    const float* bv  = (const float*)d_in[6];
    const float* Wo  = (const float*)d_in[7];
    const float* bo  = (const float*)d_in[8];
    const float* W1  = (const float*)d_in[9];
    const float* b1  = (const float*)d_in[10];
    const float* W2  = (const float*)d_in[11];
    const float* b2  = (const float*)d_in[12];
    const float* g1  = (const float*)d_in[13];
    const float* be1 = (const float*)d_in[14];
    const float* g2  = (const float*)d_in[15];
    const float* be2 = (const float*)d_in[16];
    float* out = (float*)d_out;

    float *q, *k, *v, *av, *t1, *x1, *ff, *wt;
    cudaGetSymbolAddress((void**)&q,  g_q);
    cudaGetSymbolAddress((void**)&k,  g_k);
    cudaGetSymbolAddress((void**)&v,  g_v);
    cudaGetSymbolAddress((void**)&av, g_av);
    cudaGetSymbolAddress((void**)&t1, g_t1);
    cudaGetSymbolAddress((void**)&x1, g_x1);
    cudaGetSymbolAddress((void**)&ff, g_ff);
    cudaGetSymbolAddress((void**)&wt, g_wt);

    // transpose conv weights (Wq, Wk) to [tap][co][ci]
    wtrans_kernel<<<(2 * 3 * BDIM * BDIM + 255) / 256, 256>>>(Wq, Wk, wt);

    dim3 cgrid(NTOK / 128, BDIM / 64);
    conv_mma<<<cgrid, 256>>>(src, wt,                     bq, q, 3);
    conv_mma<<<cgrid, 256>>>(src, wt + 3 * BDIM * BDIM,   bk, k, 3);
    conv_mma<<<cgrid, 256>>>(src, Wv,                     bv, v, 1);

    attn_kernel<<<dim3(SDIM / 64, NHEADS, BATCH), 256>>>(q, k, v, av);

    gemm_mma<0><<<dim3(NTOK / 128, BDIM / 64), 256>>>(av, Wo, bo, src, t1, BDIM, BDIM);
    ln_kernel<<<NTOK, 256>>>(t1, g1, be1, x1);

    gemm_mma<1><<<dim3(NTOK / 128, DFF / 64), 256>>>(x1, W1, b1, nullptr, ff, DFF, BDIM);
    gemm_mma<2><<<dim3(NTOK / 128, BDIM / 64), 256>>>(ff, W2, b2, x1, t1, BDIM, DFF);
    ln_kernel<<<NTOK, 256>>>(t1, g2, be2, out);
}

// round 3
// speedup vs baseline: 2.5218x; 1.3982x over previous
#include <cuda_runtime.h>
#include <math.h>
#include <stdint.h>

// Problem constants
#define BDIM   512
#define SDIM   1024
#define BATCH  8
#define NHEADS 8
#define HD     64
#define DFF    2048
#define NTOK   (BATCH * SDIM)   // 8192

// Scratch (device globals; no cudaMalloc allowed)
__device__ float g_q [BATCH * BDIM * SDIM];   // [B, H, S, 64]
__device__ float g_k [BATCH * BDIM * SDIM];   // [B, H, S, 64]
__device__ float g_v [BATCH * BDIM * SDIM];   // [B, D, S]
__device__ float g_av[NTOK * BDIM];           // [B*S, D]
__device__ float g_t1[NTOK * BDIM];
__device__ float g_x1[NTOK * BDIM];
__device__ float g_ff[NTOK * DFF];
__device__ float g_wt[2 * 3 * BDIM * BDIM];   // transposed Wq/Wk: [mat][tap][co][ci]

// ---------------------------------------------------------------------------
// helpers: tf32 convert + mma
// ---------------------------------------------------------------------------
__device__ __forceinline__ uint32_t f2tf(float f) {
    uint32_t r;
    asm("cvt.rna.tf32.f32 %0, %1;" : "=r"(r) : "f"(f));
    return r;
}

__device__ __forceinline__ void mma_tf32(float c[4], const uint32_t a[4], const uint32_t b[2]) {
    asm volatile(
        "mma.sync.aligned.m16n8k8.row.col.f32.tf32.tf32.f32 "
        "{%0,%1,%2,%3}, {%4,%5,%6,%7}, {%8,%9}, {%0,%1,%2,%3};"
        : "+f"(c[0]), "+f"(c[1]), "+f"(c[2]), "+f"(c[3])
        : "r"(a[0]), "r"(a[1]), "r"(a[2]), "r"(a[3]), "r"(b[0]), "r"(b[1]));
}

// ---------------------------------------------------------------------------
// Weight transpose for conv: dst[mat][tap][co][ci] = Wsrc[co][ci*3 + tap]
// ---------------------------------------------------------------------------
__global__ void wtrans_kernel(const float* __restrict__ Wq, const float* __restrict__ Wk,
                              float* __restrict__ dst) {
    int e = blockIdx.x * 256 + threadIdx.x;
    if (e >= 2 * 3 * BDIM * BDIM) return;
    int m  = (e >= 3 * BDIM * BDIM);
    int e2 = e - m * 3 * BDIM * BDIM;
    int t  = e2 >> 18;
    int co = (e2 >> 9) & 511;
    int ci = e2 & 511;
    const float* src = m ? Wk : Wq;
    dst[e] = src[(size_t)co * 1536 + ci * 3 + t];
}

// ---------------------------------------------------------------------------
// Conv as tap-accumulated tf32 tensor-core GEMM.
// A = src [NTOK, 512]; Wt slice [co][ci] per tap.
// LAYOUT 0: out[b, co, s]  ([B,D,S])   LAYOUT 1: out[b, co>>6, s, co&63] ([B,H,S,hd])
// ---------------------------------------------------------------------------
template <int LAYOUT>
__global__ __launch_bounds__(256) void conv_mma(const float* __restrict__ A,
                                                const float* __restrict__ Wt,
                                                const float* __restrict__ bias,
                                                float* __restrict__ out, int taps) {
    const int n0 = blockIdx.x * 128;
    const int c0 = blockIdx.y * 64;

    __shared__ uint32_t As[128][36];
    __shared__ uint32_t Ws[64][36];

    const int tid  = threadIdx.x;
    const int lane = tid & 31;
    const int warp = tid >> 5;
    const int wi = (warp >> 1) * 32;
    const int wj = (warp & 1) * 32;
    const int lq = lane >> 2;
    const int lr = lane & 3;

    float acc[2][4][4];
    #pragma unroll
    for (int mi = 0; mi < 2; mi++)
        #pragma unroll
        for (int ni = 0; ni < 4; ni++)
            #pragma unroll
            for (int c = 0; c < 4; c++) acc[mi][ni][c] = 0.f;

    for (int tap = 0; tap < taps; tap++) {
        const float* Wsl = Wt + (size_t)tap * BDIM * BDIM;
        const int roff = tap - (taps >> 1);

        for (int kb = 0; kb < BDIM; kb += 32) {
            #pragma unroll
            for (int r = 0; r < 4; r++) {
                int v = tid + 256 * r;
                int row = v >> 3, kc = (v & 7) * 4;
                int n = n0 + row;
                int s = (n & 1023) + roff;
                float4 val = make_float4(0.f, 0.f, 0.f, 0.f);
                if ((unsigned)s < 1024u)
                    val = *(const float4*)&A[((size_t)(n & ~1023) + s) * BDIM + kb + kc];
                As[row][kc + 0] = f2tf(val.x);
                As[row][kc + 1] = f2tf(val.y);
                As[row][kc + 2] = f2tf(val.z);
                As[row][kc + 3] = f2tf(val.w);
            }
            #pragma unroll
            for (int r = 0; r < 2; r++) {
                int v = tid + 256 * r;
                int row = v >> 3, kc = (v & 7) * 4;
                float4 val = *(const float4*)&Wsl[(size_t)(c0 + row) * BDIM + kb + kc];
                Ws[row][kc + 0] = f2tf(val.x);
                Ws[row][kc + 1] = f2tf(val.y);
                Ws[row][kc + 2] = f2tf(val.z);
                Ws[row][kc + 3] = f2tf(val.w);
            }
            __syncthreads();

            #pragma unroll
            for (int ks = 0; ks < 4; ks++) {
                const int k8 = ks * 8 + lr;
                uint32_t a[2][4], b[4][2];
                #pragma unroll
                for (int mi = 0; mi < 2; mi++) {
                    int rb = wi + mi * 16 + lq;
                    a[mi][0] = As[rb][k8];
                    a[mi][1] = As[rb + 8][k8];
                    a[mi][2] = As[rb][k8 + 4];
                    a[mi][3] = As[rb + 8][k8 + 4];
                }
                #pragma unroll
                for (int ni = 0; ni < 4; ni++) {
                    int jr = wj + ni * 8 + lq;
                    b[ni][0] = Ws[jr][k8];
                    b[ni][1] = Ws[jr][k8 + 4];
                }
                #pragma unroll
                for (int mi = 0; mi < 2; mi++)
                    #pragma unroll
                    for (int ni = 0; ni < 4; ni++)
                        mma_tf32(acc[mi][ni], a[mi], b[ni]);
            }
            __syncthreads();
        }
    }

    const int bidx = n0 >> 10;
    const int sbase = (n0 & 1023) + wi;
    #pragma unroll
    for (int mi = 0; mi < 2; mi++) {
        #pragma unroll
        for (int ni = 0; ni < 4; ni++) {
            int co = c0 + wj + ni * 8 + 2 * lr;
            float bv0 = bias[co], bv1 = bias[co + 1];
            #pragma unroll
            for (int h = 0; h < 2; h++) {
                int s = sbase + mi * 16 + lq + h * 8;
                if (LAYOUT == 0) {
                    out[((size_t)(bidx * BDIM + co)) * SDIM + s]     = acc[mi][ni][2 * h]     + bv0;
                    out[((size_t)(bidx * BDIM + co + 1)) * SDIM + s] = acc[mi][ni][2 * h + 1] + bv1;
                } else {
                    float2 o2 = make_float2(acc[mi][ni][2 * h] + bv0, acc[mi][ni][2 * h + 1] + bv1);
                    *(float2*)&out[(((size_t)(bidx * NHEADS + (co >> 6))) * SDIM + s) * HD + (co & 63)] = o2;
                }
            }
        }
    }
}

// ---------------------------------------------------------------------------
// tf32 tensor-core flash attention.
// q,k: [B,H,S,64]; v: [B,D,S]. 128 threads, 64-query tile, warp owns 16 rows.
// P tile reuses the K smem buffer (dead after the scores mma).
// ---------------------------------------------------------------------------
__global__ __launch_bounds__(128) void attn_mma(const float* __restrict__ q,
                                                const float* __restrict__ k,
                                                const float* __restrict__ v,
                                                float* __restrict__ av) {
    const int s0 = blockIdx.x * 64;
    const int h  = blockIdx.y;
    const int b  = blockIdx.z;
    const float* qb = q + (size_t)(b * NHEADS + h) * SDIM * HD;
    const float* kb = k + (size_t)(b * NHEADS + h) * SDIM * HD;
    const float* vb = v + (size_t)(b * NHEADS + h) * HD * SDIM;

    __shared__ uint32_t Ks[64][68];   // K tile, then P tile
    __shared__ uint32_t Vs[64][68];

    const int tid  = threadIdx.x;
    const int lane = tid & 31;
    const int warp = tid >> 5;     // 0..3, owns rows warp*16..+16
    const int lq = lane >> 2;      // 0..7
    const int lr = lane & 3;       // 0..3

    // Stage Q tile (scaled by 1/64) through Ks, pull fragments to registers
    #pragma unroll
    for (int r = 0; r < 8; r++) {
        int vdx = tid + 128 * r;
        int row = vdx >> 4, col = (vdx & 15) * 4;
        float4 x = *(const float4*)&qb[(size_t)(s0 + row) * HD + col];
        Ks[row][col + 0] = f2tf(x.x * 0.015625f);
        Ks[row][col + 1] = f2tf(x.y * 0.015625f);
        Ks[row][col + 2] = f2tf(x.z * 0.015625f);
        Ks[row][col + 3] = f2tf(x.w * 0.015625f);
    }
    __syncthreads();
    uint32_t qf[8][4];
    #pragma unroll
    for (int ks = 0; ks < 8; ks++) {
        int k8 = ks * 8 + lr;
        int r0 = warp * 16 + lq;
        qf[ks][0] = Ks[r0][k8];
        qf[ks][1] = Ks[r0 + 8][k8];
        qf[ks][2] = Ks[r0][k8 + 4];
        qf[ks][3] = Ks[r0 + 8][k8 + 4];
    }
    __syncthreads();

    float m0v = -1e30f, m1v = -1e30f, l0 = 0.f, l1 = 0.f;
    float o[8][4];
    #pragma unroll
    for (int ni = 0; ni < 8; ni++)
        #pragma unroll
        for (int c = 0; c < 4; c++) o[ni][c] = 0.f;

    for (int t0 = 0; t0 < SDIM; t0 += 64) {
        // Load K tile [t][d] and V tile [d][t]
        #pragma unroll
        for (int r = 0; r < 8; r++) {
            int vdx = tid + 128 * r;
            int row = vdx >> 4, col = (vdx & 15) * 4;
            float4 x = *(const float4*)&kb[(size_t)(t0 + row) * HD + col];
            Ks[row][col + 0] = f2tf(x.x);
            Ks[row][col + 1] = f2tf(x.y);
            Ks[row][col + 2] = f2tf(x.z);
            Ks[row][col + 3] = f2tf(x.w);
            float4 y = *(const float4*)&vb[(size_t)row * SDIM + t0 + col];
            Vs[row][col + 0] = f2tf(y.x);
            Vs[row][col + 1] = f2tf(y.y);
            Vs[row][col + 2] = f2tf(y.z);
            Vs[row][col + 3] = f2tf(y.w);
        }
        __syncthreads();

        // scores[16 rows][64 t]: 8 n-tiles x 8 k-steps
        float sc[8][4];
        #pragma unroll
        for (int ni = 0; ni < 8; ni++)
            #pragma unroll
            for (int c = 0; c < 4; c++) sc[ni][c] = 0.f;
        #pragma unroll
        for (int ks = 0; ks < 8; ks++) {
            int k8 = ks * 8 + lr;
            #pragma unroll
            for (int ni = 0; ni < 8; ni++) {
                uint32_t bb[2];
                bb[0] = Ks[ni * 8 + lq][k8];
                bb[1] = Ks[ni * 8 + lq][k8 + 4];
                mma_tf32(sc[ni], qf[ks], bb);
            }
        }
        __syncthreads();   // everyone done reading Ks; safe to overwrite with P

        // Online softmax (rows lq -> c0,c1 ; lq+8 -> c2,c3)
        float rm0 = -1e30f, rm1 = -1e30f;
        #pragma unroll
        for (int ni = 0; ni < 8; ni++) {
            rm0 = fmaxf(rm0, fmaxf(sc[ni][0], sc[ni][1]));
            rm1 = fmaxf(rm1, fmaxf(sc[ni][2], sc[ni][3]));
        }
        rm0 = fmaxf(rm0, __shfl_xor_sync(0xffffffffu, rm0, 1));
        rm0 = fmaxf(rm0, __shfl_xor_sync(0xffffffffu, rm0, 2));
        rm1 = fmaxf(rm1, __shfl_xor_sync(0xffffffffu, rm1, 1));
        rm1 = fmaxf(rm1, __shfl_xor_sync(0xffffffffu, rm1, 2));
        float mn0 = fmaxf(m0v, rm0), mn1 = fmaxf(m1v, rm1);
        float cr0 = __expf(m0v - mn0), cr1 = __expf(m1v - mn1);
        float rs0 = 0.f, rs1 = 0.f;
        const int prow = warp * 16 + lq;
        #pragma unroll
        for (int ni = 0; ni < 8; ni++) {
            float p0 = __expf(sc[ni][0] - mn0);
            float p1 = __expf(sc[ni][1] - mn0);
            float p2 = __expf(sc[ni][2] - mn1);
            float p3 = __expf(sc[ni][3] - mn1);
            int col = ni * 8 + 2 * lr;
            Ks[prow][col]         = f2tf(p0);
            Ks[prow][col + 1]     = f2tf(p1);
            Ks[prow + 8][col]     = f2tf(p2);
            Ks[prow + 8][col + 1] = f2tf(p3);
            rs0 += p0 + p1;
            rs1 += p2 + p3;
        }
        rs0 += __shfl_xor_sync(0xffffffffu, rs0, 1);
        rs0 += __shfl_xor_sync(0xffffffffu, rs0, 2);
        rs1 += __shfl_xor_sync(0xffffffffu, rs1, 1);
        rs1 += __shfl_xor_sync(0xffffffffu, rs1, 2);
        l0 = l0 * cr0 + rs0;
        l1 = l1 * cr1 + rs1;
        m0v = mn0; m1v = mn1;
        #pragma unroll
        for (int ni = 0; ni < 8; ni++) {
            o[ni][0] *= cr0; o[ni][1] *= cr0;
            o[ni][2] *= cr1; o[ni][3] *= cr1;
        }
        __syncwarp();   // warp reads only its own P rows

        // PV: O[16 s][64 d] += P[16 s][64 t] * V[d][t]
        #pragma unroll
        for (int ks = 0; ks < 8; ks++) {
            int k8 = ks * 8 + lr;
            uint32_t a[4];
            a[0] = Ks[prow][k8];
            a[1] = Ks[prow + 8][k8];
            a[2] = Ks[prow][k8 + 4];
            a[3] = Ks[prow + 8][k8 + 4];
            #pragma unroll
            for (int ni = 0; ni < 8; ni++) {
                uint32_t bb[2];
                bb[0] = Vs[ni * 8 + lq][k8];
                bb[1] = Vs[ni * 8 + lq][k8 + 4];
                mma_tf32(o[ni], a, bb);
            }
        }
        __syncthreads();   // before next tile overwrites Ks(P)/Vs
    }

    // Epilogue
    float inv0 = 1.0f / l0, inv1 = 1.0f / l1;
    const int rbase = s0 + warp * 16;
    #pragma unroll
    for (int ni = 0; ni < 8; ni++) {
        int col = h * HD + ni * 8 + 2 * lr;
        float2 a = make_float2(o[ni][0] * inv0, o[ni][1] * inv0);
        float2 c = make_float2(o[ni][2] * inv1, o[ni][3] * inv1);
        *(float2*)&av[(size_t)(b * SDIM + rbase + lq) * BDIM + col]     = a;
        *(float2*)&av[(size_t)(b * SDIM + rbase + lq + 8) * BDIM + col] = c;
    }
}

// ---------------------------------------------------------------------------
// Generic tf32 GEMM: out[n,m] = A[n,:].W[m,:] + bias[m] (+epilogue)
// MODE 0: +res  | MODE 1: relu | MODE 2: +res
// ---------------------------------------------------------------------------
template <int MODE>
__global__ __launch_bounds__(256) void gemm_mma(const float* __restrict__ A,
                                                const float* __restrict__ W,
                                                const float* __restrict__ bias,
                                                const float* __restrict__ res,
                                                float* __restrict__ out, int M, int K) {
    const int n0 = blockIdx.x * 128;
    const int m0 = blockIdx.y * 64;

    __shared__ uint32_t As[128][36];
    __shared__ uint32_t Ws[64][36];

    const int tid  = threadIdx.x;
    const int lane = tid & 31;
    const int warp = tid >> 5;
    const int wi = (warp >> 1) * 32;
    const int wj = (warp & 1) * 32;
    const int lq = lane >> 2;
    const int lr = lane & 3;

    float acc[2][4][4];
    #pragma unroll
    for (int mi = 0; mi < 2; mi++)
        #pragma unroll
        for (int ni = 0; ni < 4; ni++)
            #pragma unroll
            for (int c = 0; c < 4; c++) acc[mi][ni][c] = 0.f;

    for (int kb = 0; kb < K; kb += 32) {
        #pragma unroll
        for (int r = 0; r < 4; r++) {
            int v = tid + 256 * r;
            int row = v >> 3, kc = (v & 7) * 4;
            float4 val = *(const float4*)&A[(size_t)(n0 + row) * K + kb + kc];
            As[row][kc + 0] = f2tf(val.x);
            As[row][kc + 1] = f2tf(val.y);
            As[row][kc + 2] = f2tf(val.z);
            As[row][kc + 3] = f2tf(val.w);
        }
        #pragma unroll
        for (int r = 0; r < 2; r++) {
            int v = tid + 256 * r;
            int row = v >> 3, kc = (v & 7) * 4;
            float4 val = *(const float4*)&W[(size_t)(m0 + row) * K + kb + kc];
            Ws[row][kc + 0] = f2tf(val.x);
            Ws[row][kc + 1] = f2tf(val.y);
            Ws[row][kc + 2] = f2tf(val.z);
            Ws[row][kc + 3] = f2tf(val.w);
        }
        __syncthreads();

        #pragma unroll
        for (int ks = 0; ks < 4; ks++) {
            const int k8 = ks * 8 + lr;
            uint32_t a[2][4], b[4][2];
            #pragma unroll
            for (int mi = 0; mi < 2; mi++) {
                int rb = wi + mi * 16 + lq;
                a[mi][0] = As[rb][k8];
                a[mi][1] = As[rb + 8][k8];
                a[mi][2] = As[rb][k8 + 4];
                a[mi][3] = As[rb + 8][k8 + 4];
            }
            #pragma unroll
            for (int ni = 0; ni < 4; ni++) {
                int jr = wj + ni * 8 + lq;
                b[ni][0] = Ws[jr][k8];
                b[ni][1] = Ws[jr][k8 + 4];
            }
            #pragma unroll
            for (int mi = 0; mi < 2; mi++)
                #pragma unroll
                for (int ni = 0; ni < 4; ni++)
                    mma_tf32(acc[mi][ni], a[mi], b[ni]);
        }
        __syncthreads();
    }

    #pragma unroll
    for (int mi = 0; mi < 2; mi++) {
        #pragma unroll
        for (int ni = 0; ni < 4; ni++) {
            int col = m0 + wj + ni * 8 + 2 * lr;
            float bv0 = bias[col], bv1 = bias[col + 1];
            #pragma unroll
            for (int h = 0; h < 2; h++) {
                int n = n0 + wi + mi * 16 + lq + h * 8;
                float x0 = acc[mi][ni][2 * h] + bv0;
                float x1 = acc[mi][ni][2 * h + 1] + bv1;
                if (MODE == 1) { x0 = fmaxf(x0, 0.f); x1 = fmaxf(x1, 0.f); }
                if (MODE == 0 || MODE == 2) {
                    x0 += res[(size_t)n * M + col];
                    x1 += res[(size_t)n * M + col + 1];
                }
                float2 o2 = make_float2(x0, x1);
                *(float2*)&out[(size_t)n * M + col] = o2;
            }
        }
    }
}

// ---------------------------------------------------------------------------
// LayerNorm over last dim (512). One block per row, 256 threads.
// ---------------------------------------------------------------------------
__global__ void ln_kernel(const float* __restrict__ in, const float* __restrict__ g,
                          const float* __restrict__ beta, float* __restrict__ out) {
    const int row = blockIdx.x;
    const float* x = in + (size_t)row * BDIM;
    const int tid = threadIdx.x;
    const int wid = tid >> 5, lane = tid & 31;

    float v0 = x[tid], v1 = x[tid + 256];

    __shared__ float red[8];

    float s = v0 + v1;
    #pragma unroll
    for (int off = 16; off > 0; off >>= 1)
        s += __shfl_xor_sync(0xffffffffu, s, off);
    if (lane == 0) red[wid] = s;
    __syncthreads();
    float tot = 0.f;
    #pragma unroll
    for (int i = 0; i < 8; i++) tot += red[i];
    float mu = tot * (1.0f / 512.0f);
    __syncthreads();

    float d0 = v0 - mu, d1 = v1 - mu;
    float sq = d0 * d0 + d1 * d1;
    #pragma unroll
    for (int off = 16; off > 0; off >>= 1)
        sq += __shfl_xor_sync(0xffffffffu, sq, off);
    if (lane == 0) red[wid] = sq;
    __syncthreads();
    float tot2 = 0.f;
    #pragma unroll
    for (int i = 0; i < 8; i++) tot2 += red[i];
    float rstd = rsqrtf(tot2 * (1.0f / 512.0f) + 1e-5f);

    out[(size_t)row * BDIM + tid]       = d0 * rstd * g[tid]       + beta[tid];
    out[(size_t)row * BDIM + tid + 256] = d1 * rstd * g[tid + 256] + beta[tid + 256];
}

// ---------------------------------------------------------------------------
extern "C" void kernel_launch(void* const* d_in, const int* in_sizes, int n_in,
                              void* d_out, int out_size) {
    const float* src = (const float*)d_in[0];
    const float* Wq  = (const float*)d_in[1];
    const float* bq  = (const float*)d_in[2];
    const float* Wk  = (const float*)d_in[3];
    const float* bk  = (const float*)d_in[4];
    const float* Wv  = (const float*)d_in[5];
    const float* bv  = (const float*)d_in[6];
    const float* Wo  = (const float*)d_in[7];
    const float* bo  = (const float*)d_in[8];
    const float* W1  = (const float*)d_in[9];
    const float* b1  = (const float*)d_in[10];
    const float* W2  = (const float*)d_in[11];
    const float* b2  = (const float*)d_in[12];
    const float* g1  = (const float*)d_in[13];
    const float* be1 = (const float*)d_in[14];
    const float* g2  = (const float*)d_in[15];
    const float* be2 = (const float*)d_in[16];
    float* out = (float*)d_out;

    float *q, *k, *v, *av, *t1, *x1, *ff, *wt;
    cudaGetSymbolAddress((void**)&q,  g_q);
    cudaGetSymbolAddress((void**)&k,  g_k);
    cudaGetSymbolAddress((void**)&v,  g_v);
    cudaGetSymbolAddress((void**)&av, g_av);
    cudaGetSymbolAddress((void**)&t1, g_t1);
    cudaGetSymbolAddress((void**)&x1, g_x1);
    cudaGetSymbolAddress((void**)&ff, g_ff);
    cudaGetSymbolAddress((void**)&wt, g_wt);

    wtrans_kernel<<<(2 * 3 * BDIM * BDIM + 255) / 256, 256>>>(Wq, Wk, wt);

    dim3 cgrid(NTOK / 128, BDIM / 64);
    conv_mma<1><<<cgrid, 256>>>(src, wt,                   bq, q, 3);
    conv_mma<1><<<cgrid, 256>>>(src, wt + 3 * BDIM * BDIM, bk, k, 3);
    conv_mma<0><<<cgrid, 256>>>(src, Wv,                   bv, v, 1);

    attn_mma<<<dim3(SDIM / 64, NHEADS, BATCH), 128>>>(q, k, v, av);

    gemm_mma<0><<<dim3(NTOK / 128, BDIM / 64), 256>>>(av, Wo, bo, src, t1, BDIM, BDIM);
    ln_kernel<<<NTOK, 256>>>(t1, g1, be1, x1);

    gemm_mma<1><<<dim3(NTOK / 128, DFF / 64), 256>>>(x1, W1, b1, nullptr, ff, DFF, BDIM);
    gemm_mma<2><<<dim3(NTOK / 128, BDIM / 64), 256>>>(ff, W2, b2, x1, t1, BDIM, DFF);
    ln_kernel<<<NTOK, 256>>>(t1, g2, be2, out);
}

// round 4
// speedup vs baseline: 2.9139x; 1.1555x over previous
#include <cuda_runtime.h>
#include <math.h>
#include <stdint.h>

#define BDIM   512
#define SDIM   1024
#define BATCH  8
#define NHEADS 8
#define HD     64
#define DFF    2048
#define NTOK   (BATCH * SDIM)   // 8192

// Scratch
__device__ float    g_q [BATCH * BDIM * SDIM];   // [B,H,S,64]
__device__ float    g_k [BATCH * BDIM * SDIM];   // [B,H,S,64]
__device__ float    g_v [BATCH * BDIM * SDIM];   // [B,D,S]
__device__ float    g_av[NTOK * BDIM];
__device__ float    g_t1[NTOK * BDIM];
__device__ float    g_x1[NTOK * BDIM];
__device__ float    g_ff[NTOK * DFF];
__device__ uint32_t g_wt[2 * 3 * BDIM * BDIM];   // tf32 Wq/Wk: [mat][tap][co][ci]
__device__ uint32_t g_wc[2 * BDIM * BDIM + 2 * DFF * BDIM];  // tf32 Wv,Wo,W1,W2

#define WC_WV 0
#define WC_WO (BDIM * BDIM)
#define WC_W1 (2 * BDIM * BDIM)
#define WC_W2 (2 * BDIM * BDIM + DFF * BDIM)

__device__ __forceinline__ uint32_t f2tf(float f) {
    uint32_t r;
    asm("cvt.rna.tf32.f32 %0, %1;" : "=r"(r) : "f"(f));
    return r;
}

__device__ __forceinline__ void mma_tf32(float c[4], const uint32_t a[4], const uint32_t b[2]) {
    asm volatile(
        "mma.sync.aligned.m16n8k8.row.col.f32.tf32.tf32.f32 "
        "{%0,%1,%2,%3}, {%4,%5,%6,%7}, {%8,%9}, {%0,%1,%2,%3};"
        : "+f"(c[0]), "+f"(c[1]), "+f"(c[2]), "+f"(c[3])
        : "r"(a[0]), "r"(a[1]), "r"(a[2]), "r"(a[3]), "r"(b[0]), "r"(b[1]));
}

// ---------------------------------------------------------------------------
// Prep: transpose+convert Wq/Wk to tf32 [mat][tap][co][ci]
// ---------------------------------------------------------------------------
__global__ void wtrans_kernel(const float* __restrict__ Wq, const float* __restrict__ Wk,
                              uint32_t* __restrict__ dst) {
    int e = blockIdx.x * 256 + threadIdx.x;
    if (e >= 2 * 3 * BDIM * BDIM) return;
    int m  = (e >= 3 * BDIM * BDIM);
    int e2 = e - m * 3 * BDIM * BDIM;
    int t  = e2 >> 18;
    int co = (e2 >> 9) & 511;
    int ci = e2 & 511;
    const float* src = m ? Wk : Wq;
    dst[e] = f2tf(src[(size_t)co * 1536 + ci * 3 + t]);
}

// Prep: elementwise f32 -> tf32
__global__ void wconv_kernel(const float* __restrict__ src, uint32_t* __restrict__ dst, int n) {
    int e = blockIdx.x * 256 + threadIdx.x;
    if (e < n) dst[e] = f2tf(src[e]);
}

// ===========================================================================
// GEMM core v2: block 128(n) x 64(m), 8 warps (32x32 each), KT=32,
// fragment-major XOR-swizzled smem, double-buffered, one barrier per stage.
// MODE 0: +res | 1: relu | 2: +res | 3: V-conv layout [B,D,S] (bias only)
// A: f32 (cvt at STS). W: preconverted tf32.
// ===========================================================================
template <int MODE>
__global__ __launch_bounds__(256) void gemm2(const float* __restrict__ A,
                                             const uint32_t* __restrict__ W,
                                             const float* __restrict__ bias,
                                             const float* __restrict__ res,
                                             float* __restrict__ out, int M, int K) {
    __shared__ uint4 Af[2][8][4][32];   // [st][rb16][ks][lane] 32KB
    __shared__ uint2 Bf[2][8][4][32];   // [st][nb8][ks][lane]  16KB

    const int n0 = blockIdx.x * 128;
    const int m0 = blockIdx.y * 64;
    const int tid = threadIdx.x, lane = tid & 31, warp = tid >> 5;
    const int lq = lane >> 2, lr = lane & 3;
    const int wiB = (warp >> 1) * 2;    // rowblock16 base
    const int wjB = (warp & 1) * 4;     // nb base
    const int nk = K >> 5;

    float acc[2][4][4];
    #pragma unroll
    for (int mi = 0; mi < 2; mi++)
        #pragma unroll
        for (int ni = 0; ni < 4; ni++)
            #pragma unroll
            for (int c = 0; c < 4; c++) acc[mi][ni][c] = 0.f;

    float4 sa[4];
    uint4  sb[2];

    // ---- preload stage 0 ----
    #pragma unroll
    for (int r = 0; r < 4; r++) {
        int v = tid + 256 * r;
        sa[r] = *(const float4*)&A[(size_t)(n0 + (v >> 3)) * K + (v & 7) * 4];
    }
    #pragma unroll
    for (int r = 0; r < 2; r++) {
        int v = tid + 256 * r;
        sb[r] = *(const uint4*)&W[(size_t)(m0 + (v >> 3)) * K + (v & 7) * 4];
    }
    {
        #pragma unroll
        for (int r = 0; r < 4; r++) {
            int v = tid + 256 * r;
            int row = v >> 3, kc4 = v & 7;
            int ks = kc4 >> 1, half = kc4 & 1, rb = row >> 4, alq = row & 7, r8 = (row >> 3) & 1;
            int comp = r8 + 2 * half;
            uint32_t* base = (uint32_t*)&Af[0][rb][ks][0];
            uint32_t vals[4] = {f2tf(sa[r].x), f2tf(sa[r].y), f2tf(sa[r].z), f2tf(sa[r].w)};
            #pragma unroll
            for (int e = 0; e < 4; e++) base[(((alq * 4 + e) ^ ks) << 2) + comp] = vals[e];
        }
        #pragma unroll
        for (int r = 0; r < 2; r++) {
            int v = tid + 256 * r;
            int row = v >> 3, kc4 = v & 7;
            int ks = kc4 >> 1, half = kc4 & 1, nb = row >> 3, blq = row & 7;
            uint32_t* base = (uint32_t*)&Bf[0][nb][ks][0];
            uint32_t vals[4] = {sb[r].x, sb[r].y, sb[r].z, sb[r].w};
            #pragma unroll
            for (int e = 0; e < 4; e++) base[(((blq * 4 + e) ^ ks) << 1) + half] = vals[e];
        }
    }
    __syncthreads();

    for (int kb = 0; kb < nk; kb++) {
        if (kb + 1 < nk) {
            int ko = (kb + 1) << 5;
            #pragma unroll
            for (int r = 0; r < 4; r++) {
                int v = tid + 256 * r;
                sa[r] = *(const float4*)&A[(size_t)(n0 + (v >> 3)) * K + ko + (v & 7) * 4];
            }
            #pragma unroll
            for (int r = 0; r < 2; r++) {
                int v = tid + 256 * r;
                sb[r] = *(const uint4*)&W[(size_t)(m0 + (v >> 3)) * K + ko + (v & 7) * 4];
            }
        }

        // compute current stage
        {
            const int st = kb & 1;
            #pragma unroll
            for (int ks = 0; ks < 4; ks++) {
                uint4 a0 = Af[st][wiB][ks][lane ^ ks];
                uint4 a1 = Af[st][wiB + 1][ks][lane ^ ks];
                uint32_t aa0[4] = {a0.x, a0.y, a0.z, a0.w};
                uint32_t aa1[4] = {a1.x, a1.y, a1.z, a1.w};
                #pragma unroll
                for (int ni = 0; ni < 4; ni++) {
                    uint2 b = Bf[st][wjB + ni][ks][lane ^ ks];
                    uint32_t bb[2] = {b.x, b.y};
                    mma_tf32(acc[0][ni], aa0, bb);
                    mma_tf32(acc[1][ni], aa1, bb);
                }
            }
        }

        if (kb + 1 < nk) {
            const int st = (kb + 1) & 1;
            #pragma unroll
            for (int r = 0; r < 4; r++) {
                int v = tid + 256 * r;
                int row = v >> 3, kc4 = v & 7;
                int ks = kc4 >> 1, half = kc4 & 1, rb = row >> 4, alq = row & 7, r8 = (row >> 3) & 1;
                int comp = r8 + 2 * half;
                uint32_t* base = (uint32_t*)&Af[st][rb][ks][0];
                uint32_t vals[4] = {f2tf(sa[r].x), f2tf(sa[r].y), f2tf(sa[r].z), f2tf(sa[r].w)};
                #pragma unroll
                for (int e = 0; e < 4; e++) base[(((alq * 4 + e) ^ ks) << 2) + comp] = vals[e];
            }
            #pragma unroll
            for (int r = 0; r < 2; r++) {
                int v = tid + 256 * r;
                int row = v >> 3, kc4 = v & 7;
                int ks = kc4 >> 1, half = kc4 & 1, nb = row >> 3, blq = row & 7;
                uint32_t* base = (uint32_t*)&Bf[st][nb][ks][0];
                uint32_t vals[4] = {sb[r].x, sb[r].y, sb[r].z, sb[r].w};
                #pragma unroll
                for (int e = 0; e < 4; e++) base[(((blq * 4 + e) ^ ks) << 1) + half] = vals[e];
            }
        }
        __syncthreads();
    }

    // Epilogue
    #pragma unroll
    for (int mi = 0; mi < 2; mi++) {
        #pragma unroll
        for (int ni = 0; ni < 4; ni++) {
            int col = m0 + (warp & 1) * 32 + ni * 8 + 2 * lr;
            float bv0 = bias[col], bv1 = bias[col + 1];
            #pragma unroll
            for (int h = 0; h < 2; h++) {
                int n = n0 + (warp >> 1) * 32 + mi * 16 + lq + h * 8;
                float x0 = acc[mi][ni][2 * h] + bv0;
                float x1 = acc[mi][ni][2 * h + 1] + bv1;
                if (MODE == 1) { x0 = fmaxf(x0, 0.f); x1 = fmaxf(x1, 0.f); }
                if (MODE == 0 || MODE == 2) {
                    x0 += res[(size_t)n * M + col];
                    x1 += res[(size_t)n * M + col + 1];
                }
                if (MODE == 3) {
                    int b = n >> 10, s = n & 1023;
                    out[((size_t)(b * BDIM + col)) * SDIM + s]     = x0;
                    out[((size_t)(b * BDIM + col + 1)) * SDIM + s] = x1;
                } else {
                    *(float2*)&out[(size_t)n * M + col] = make_float2(x0, x1);
                }
            }
        }
    }
}

// ===========================================================================
// Fused Q+K conv: block 128(tok) x 32(co) x 2 matrices, 8 warps (16 rows each),
// taps=3, same fragment-major pipelined core. Outputs [B,H,S,64].
// ===========================================================================
__global__ __launch_bounds__(256) void convqk(const float* __restrict__ A,
                                              const uint32_t* __restrict__ Wt,  // [2][3][512][512]
                                              const float* __restrict__ bq,
                                              const float* __restrict__ bk,
                                              float* __restrict__ qo,
                                              float* __restrict__ ko) {
    __shared__ uint4 Af[2][8][4][32];        // 32KB
    __shared__ uint2 Bf[2][2][4][4][32];     // [st][mat][nb4][ks][lane] 16KB

    const int n0 = blockIdx.x * 128;
    const int c0 = blockIdx.y * 32;
    const int tid = threadIdx.x, lane = tid & 31, warp = tid >> 5;
    const int lq = lane >> 2, lr = lane & 3;
    const int NST = 48;  // 3 taps x 16 kb

    float acc[2][4][4];
    #pragma unroll
    for (int m = 0; m < 2; m++)
        #pragma unroll
        for (int ni = 0; ni < 4; ni++)
            #pragma unroll
            for (int c = 0; c < 4; c++) acc[m][ni][c] = 0.f;

    float4 sa[4];
    uint4  sb[2];

    // loader helpers inline: stage t -> tap = t>>4, ko = (t&15)<<5, roff = tap-1
    // ---- preload stage 0 (tap 0, roff=-1) ----
    #pragma unroll
    for (int r = 0; r < 4; r++) {
        int v = tid + 256 * r;
        int row = v >> 3;
        int n = n0 + row;
        int s = (n & 1023) - 1;
        sa[r] = make_float4(0.f, 0.f, 0.f, 0.f);
        if (s >= 0)
            sa[r] = *(const float4*)&A[((size_t)(n & ~1023) + s) * BDIM + (v & 7) * 4];
    }
    #pragma unroll
    for (int m = 0; m < 2; m++) {
        int row = tid >> 3;
        sb[m] = *(const uint4*)&Wt[((size_t)m * 3 * BDIM + c0 + row) * BDIM + (tid & 7) * 4];
    }
    {
        #pragma unroll
        for (int r = 0; r < 4; r++) {
            int v = tid + 256 * r;
            int row = v >> 3, kc4 = v & 7;
            int ks = kc4 >> 1, half = kc4 & 1, rb = row >> 4, alq = row & 7, r8 = (row >> 3) & 1;
            int comp = r8 + 2 * half;
            uint32_t* base = (uint32_t*)&Af[0][rb][ks][0];
            uint32_t vals[4] = {f2tf(sa[r].x), f2tf(sa[r].y), f2tf(sa[r].z), f2tf(sa[r].w)};
            #pragma unroll
            for (int e = 0; e < 4; e++) base[(((alq * 4 + e) ^ ks) << 2) + comp] = vals[e];
        }
        int row = tid >> 3, kc4 = tid & 7;
        int ks = kc4 >> 1, half = kc4 & 1, nb = row >> 3, blq = row & 7;
        #pragma unroll
        for (int m = 0; m < 2; m++) {
            uint32_t* base = (uint32_t*)&Bf[0][m][nb][ks][0];
            uint32_t vals[4] = {sb[m].x, sb[m].y, sb[m].z, sb[m].w};
            #pragma unroll
            for (int e = 0; e < 4; e++) base[(((blq * 4 + e) ^ ks) << 1) + half] = vals[e];
        }
    }
    __syncthreads();

    for (int t = 0; t < NST; t++) {
        if (t + 1 < NST) {
            int tap = (t + 1) >> 4;
            int ko  = ((t + 1) & 15) << 5;
            int roff = tap - 1;
            #pragma unroll
            for (int r = 0; r < 4; r++) {
                int v = tid + 256 * r;
                int row = v >> 3;
                int n = n0 + row;
                int s = (n & 1023) + roff;
                sa[r] = make_float4(0.f, 0.f, 0.f, 0.f);
                if ((unsigned)s < 1024u)
                    sa[r] = *(const float4*)&A[((size_t)(n & ~1023) + s) * BDIM + ko + (v & 7) * 4];
            }
            int row = tid >> 3;
            #pragma unroll
            for (int m = 0; m < 2; m++)
                sb[m] = *(const uint4*)&Wt[((size_t)(m * 3 + tap) * BDIM + c0 + row) * BDIM + ko + (tid & 7) * 4];
        }

        {
            const int st = t & 1;
            #pragma unroll
            for (int ks = 0; ks < 4; ks++) {
                uint4 a = Af[st][warp][ks][lane ^ ks];
                uint32_t aa[4] = {a.x, a.y, a.z, a.w};
                #pragma unroll
                for (int m = 0; m < 2; m++)
                    #pragma unroll
                    for (int ni = 0; ni < 4; ni++) {
                        uint2 b = Bf[st][m][ni][ks][lane ^ ks];
                        uint32_t bb[2] = {b.x, b.y};
                        mma_tf32(acc[m][ni], aa, bb);
                    }
            }
        }

        if (t + 1 < NST) {
            const int st = (t + 1) & 1;
            #pragma unroll
            for (int r = 0; r < 4; r++) {
                int v = tid + 256 * r;
                int row = v >> 3, kc4 = v & 7;
                int ks = kc4 >> 1, half = kc4 & 1, rb = row >> 4, alq = row & 7, r8 = (row >> 3) & 1;
                int comp = r8 + 2 * half;
                uint32_t* base = (uint32_t*)&Af[st][rb][ks][0];
                uint32_t vals[4] = {f2tf(sa[r].x), f2tf(sa[r].y), f2tf(sa[r].z), f2tf(sa[r].w)};
                #pragma unroll
                for (int e = 0; e < 4; e++) base[(((alq * 4 + e) ^ ks) << 2) + comp] = vals[e];
            }
            int row = tid >> 3, kc4 = tid & 7;
            int ks = kc4 >> 1, half = kc4 & 1, nb = row >> 3, blq = row & 7;
            #pragma unroll
            for (int m = 0; m < 2; m++) {
                uint32_t* base = (uint32_t*)&Bf[st][m][nb][ks][0];
                uint32_t vals[4] = {sb[m].x, sb[m].y, sb[m].z, sb[m].w};
                #pragma unroll
                for (int e = 0; e < 4; e++) base[(((blq * 4 + e) ^ ks) << 1) + half] = vals[e];
            }
        }
        __syncthreads();
    }

    // Epilogue -> [B,H,S,64]
    #pragma unroll
    for (int m = 0; m < 2; m++) {
        float* outp = m ? ko : qo;
        const float* bp = m ? bk : bq;
        #pragma unroll
        for (int ni = 0; ni < 4; ni++) {
            int col = c0 + ni * 8 + 2 * lr;
            float bv0 = bp[col], bv1 = bp[col + 1];
            int hh = col >> 6, dd = col & 63;
            #pragma unroll
            for (int h = 0; h < 2; h++) {
                int n = n0 + warp * 16 + lq + h * 8;
                int b = n >> 10, s = n & 1023;
                float2 o2 = make_float2(acc[m][ni][2 * h] + bv0, acc[m][ni][2 * h + 1] + bv1);
                *(float2*)&outp[(((size_t)(b * NHEADS + hh)) * SDIM + s) * HD + dd] = o2;
            }
        }
    }
}

// ---------------------------------------------------------------------------
// tf32 tensor-core flash attention (unchanged from R3).
// ---------------------------------------------------------------------------
__global__ __launch_bounds__(128) void attn_mma(const float* __restrict__ q,
                                                const float* __restrict__ k,
                                                const float* __restrict__ v,
                                                float* __restrict__ av) {
    const int s0 = blockIdx.x * 64;
    const int h  = blockIdx.y;
    const int b  = blockIdx.z;
    const float* qb = q + (size_t)(b * NHEADS + h) * SDIM * HD;
    const float* kb = k + (size_t)(b * NHEADS + h) * SDIM * HD;
    const float* vb = v + (size_t)(b * NHEADS + h) * HD * SDIM;

    __shared__ uint32_t Ks[64][68];
    __shared__ uint32_t Vs[64][68];

    const int tid  = threadIdx.x;
    const int lane = tid & 31;
    const int warp = tid >> 5;
    const int lq = lane >> 2;
    const int lr = lane & 3;

    #pragma unroll
    for (int r = 0; r < 8; r++) {
        int vdx = tid + 128 * r;
        int row = vdx >> 4, col = (vdx & 15) * 4;
        float4 x = *(const float4*)&qb[(size_t)(s0 + row) * HD + col];
        Ks[row][col + 0] = f2tf(x.x * 0.015625f);
        Ks[row][col + 1] = f2tf(x.y * 0.015625f);
        Ks[row][col + 2] = f2tf(x.z * 0.015625f);
        Ks[row][col + 3] = f2tf(x.w * 0.015625f);
    }
    __syncthreads();
    uint32_t qf[8][4];
    #pragma unroll
    for (int ks = 0; ks < 8; ks++) {
        int k8 = ks * 8 + lr;
        int r0 = warp * 16 + lq;
        qf[ks][0] = Ks[r0][k8];
        qf[ks][1] = Ks[r0 + 8][k8];
        qf[ks][2] = Ks[r0][k8 + 4];
        qf[ks][3] = Ks[r0 + 8][k8 + 4];
    }
    __syncthreads();

    float m0v = -1e30f, m1v = -1e30f, l0 = 0.f, l1 = 0.f;
    float o[8][4];
    #pragma unroll
    for (int ni = 0; ni < 8; ni++)
        #pragma unroll
        for (int c = 0; c < 4; c++) o[ni][c] = 0.f;

    for (int t0 = 0; t0 < SDIM; t0 += 64) {
        #pragma unroll
        for (int r = 0; r < 8; r++) {
            int vdx = tid + 128 * r;
            int row = vdx >> 4, col = (vdx & 15) * 4;
            float4 x = *(const float4*)&kb[(size_t)(t0 + row) * HD + col];
            Ks[row][col + 0] = f2tf(x.x);
            Ks[row][col + 1] = f2tf(x.y);
            Ks[row][col + 2] = f2tf(x.z);
            Ks[row][col + 3] = f2tf(x.w);
            float4 y = *(const float4*)&vb[(size_t)row * SDIM + t0 + col];
            Vs[row][col + 0] = f2tf(y.x);
            Vs[row][col + 1] = f2tf(y.y);
            Vs[row][col + 2] = f2tf(y.z);
            Vs[row][col + 3] = f2tf(y.w);
        }
        __syncthreads();

        float sc[8][4];
        #pragma unroll
        for (int ni = 0; ni < 8; ni++)
            #pragma unroll
            for (int c = 0; c < 4; c++) sc[ni][c] = 0.f;
        #pragma unroll
        for (int ks = 0; ks < 8; ks++) {
            int k8 = ks * 8 + lr;
            #pragma unroll
            for (int ni = 0; ni < 8; ni++) {
                uint32_t bb[2];
                bb[0] = Ks[ni * 8 + lq][k8];
                bb[1] = Ks[ni * 8 + lq][k8 + 4];
                mma_tf32(sc[ni], qf[ks], bb);
            }
        }
        __syncthreads();

        float rm0 = -1e30f, rm1 = -1e30f;
        #pragma unroll
        for (int ni = 0; ni < 8; ni++) {
            rm0 = fmaxf(rm0, fmaxf(sc[ni][0], sc[ni][1]));
            rm1 = fmaxf(rm1, fmaxf(sc[ni][2], sc[ni][3]));
        }
        rm0 = fmaxf(rm0, __shfl_xor_sync(0xffffffffu, rm0, 1));
        rm0 = fmaxf(rm0, __shfl_xor_sync(0xffffffffu, rm0, 2));
        rm1 = fmaxf(rm1, __shfl_xor_sync(0xffffffffu, rm1, 1));
        rm1 = fmaxf(rm1, __shfl_xor_sync(0xffffffffu, rm1, 2));
        float mn0 = fmaxf(m0v, rm0), mn1 = fmaxf(m1v, rm1);
        float cr0 = __expf(m0v - mn0), cr1 = __expf(m1v - mn1);
        float rs0 = 0.f, rs1 = 0.f;
        const int prow = warp * 16 + lq;
        #pragma unroll
        for (int ni = 0; ni < 8; ni++) {
            float p0 = __expf(sc[ni][0] - mn0);
            float p1 = __expf(sc[ni][1] - mn0);
            float p2 = __expf(sc[ni][2] - mn1);
            float p3 = __expf(sc[ni][3] - mn1);
            int col = ni * 8 + 2 * lr;
            Ks[prow][col]         = f2tf(p0);
            Ks[prow][col + 1]     = f2tf(p1);
            Ks[prow + 8][col]     = f2tf(p2);
            Ks[prow + 8][col + 1] = f2tf(p3);
            rs0 += p0 + p1;
            rs1 += p2 + p3;
        }
        rs0 += __shfl_xor_sync(0xffffffffu, rs0, 1);
        rs0 += __shfl_xor_sync(0xffffffffu, rs0, 2);
        rs1 += __shfl_xor_sync(0xffffffffu, rs1, 1);
        rs1 += __shfl_xor_sync(0xffffffffu, rs1, 2);
        l0 = l0 * cr0 + rs0;
        l1 = l1 * cr1 + rs1;
        m0v = mn0; m1v = mn1;
        #pragma unroll
        for (int ni = 0; ni < 8; ni++) {
            o[ni][0] *= cr0; o[ni][1] *= cr0;
            o[ni][2] *= cr1; o[ni][3] *= cr1;
        }
        __syncwarp();

        #pragma unroll
        for (int ks = 0; ks < 8; ks++) {
            int k8 = ks * 8 + lr;
            uint32_t a[4];
            a[0] = Ks[prow][k8];
            a[1] = Ks[prow + 8][k8];
            a[2] = Ks[prow][k8 + 4];
            a[3] = Ks[prow + 8][k8 + 4];
            #pragma unroll
            for (int ni = 0; ni < 8; ni++) {
                uint32_t bb[2];
                bb[0] = Vs[ni * 8 + lq][k8];
                bb[1] = Vs[ni * 8 + lq][k8 + 4];
                mma_tf32(o[ni], a, bb);
            }
        }
        __syncthreads();
    }

    float inv0 = 1.0f / l0, inv1 = 1.0f / l1;
    const int rbase = s0 + warp * 16;
    #pragma unroll
    for (int ni = 0; ni < 8; ni++) {
        int col = h * HD + ni * 8 + 2 * lr;
        float2 a = make_float2(o[ni][0] * inv0, o[ni][1] * inv0);
        float2 c = make_float2(o[ni][2] * inv1, o[ni][3] * inv1);
        *(float2*)&av[(size_t)(b * SDIM + rbase + lq) * BDIM + col]     = a;
        *(float2*)&av[(size_t)(b * SDIM + rbase + lq + 8) * BDIM + col] = c;
    }
}

// ---------------------------------------------------------------------------
// LayerNorm over last dim (512).
// ---------------------------------------------------------------------------
__global__ void ln_kernel(const float* __restrict__ in, const float* __restrict__ g,
                          const float* __restrict__ beta, float* __restrict__ out) {
    const int row = blockIdx.x;
    const float* x = in + (size_t)row * BDIM;
    const int tid = threadIdx.x;
    const int wid = tid >> 5, lane = tid & 31;

    float v0 = x[tid], v1 = x[tid + 256];
    __shared__ float red[8];

    float s = v0 + v1;
    #pragma unroll
    for (int off = 16; off > 0; off >>= 1)
        s += __shfl_xor_sync(0xffffffffu, s, off);
    if (lane == 0) red[wid] = s;
    __syncthreads();
    float tot = 0.f;
    #pragma unroll
    for (int i = 0; i < 8; i++) tot += red[i];
    float mu = tot * (1.0f / 512.0f);
    __syncthreads();

    float d0 = v0 - mu, d1 = v1 - mu;
    float sq = d0 * d0 + d1 * d1;
    #pragma unroll
    for (int off = 16; off > 0; off >>= 1)
        sq += __shfl_xor_sync(0xffffffffu, sq, off);
    if (lane == 0) red[wid] = sq;
    __syncthreads();
    float tot2 = 0.f;
    #pragma unroll
    for (int i = 0; i < 8; i++) tot2 += red[i];
    float rstd = rsqrtf(tot2 * (1.0f / 512.0f) + 1e-5f);

    out[(size_t)row * BDIM + tid]       = d0 * rstd * g[tid]       + beta[tid];
    out[(size_t)row * BDIM + tid + 256] = d1 * rstd * g[tid + 256] + beta[tid + 256];
}

// ---------------------------------------------------------------------------
extern "C" void kernel_launch(void* const* d_in, const int* in_sizes, int n_in,
                              void* d_out, int out_size) {
    const float* src = (const float*)d_in[0];
    const float* Wq  = (const float*)d_in[1];
    const float* bq  = (const float*)d_in[2];
    const float* Wk  = (const float*)d_in[3];
    const float* bk  = (const float*)d_in[4];
    const float* Wv  = (const float*)d_in[5];
    const float* bv  = (const float*)d_in[6];
    const float* Wo  = (const float*)d_in[7];
    const float* bo  = (const float*)d_in[8];
    const float* W1  = (const float*)d_in[9];
    const float* b1  = (const float*)d_in[10];
    const float* W2  = (const float*)d_in[11];
    const float* b2  = (const float*)d_in[12];
    const float* g1  = (const float*)d_in[13];
    const float* be1 = (const float*)d_in[14];
    const float* g2  = (const float*)d_in[15];
    const float* be2 = (const float*)d_in[16];
    float* out = (float*)d_out;

    float *q, *k, *v, *av, *t1, *x1, *ff;
    uint32_t *wt, *wc;
    cudaGetSymbolAddress((void**)&q,  g_q);
    cudaGetSymbolAddress((void**)&k,  g_k);
    cudaGetSymbolAddress((void**)&v,  g_v);
    cudaGetSymbolAddress((void**)&av, g_av);
    cudaGetSymbolAddress((void**)&t1, g_t1);
    cudaGetSymbolAddress((void**)&x1, g_x1);
    cudaGetSymbolAddress((void**)&ff, g_ff);
    cudaGetSymbolAddress((void**)&wt, g_wt);
    cudaGetSymbolAddress((void**)&wc, g_wc);

    // Prep: tf32 weight conversions
    wtrans_kernel<<<(2 * 3 * BDIM * BDIM + 255) / 256, 256>>>(Wq, Wk, wt);
    wconv_kernel<<<(BDIM * BDIM + 255) / 256, 256>>>(Wv, wc + WC_WV, BDIM * BDIM);
    wconv_kernel<<<(BDIM * BDIM + 255) / 256, 256>>>(Wo, wc + WC_WO, BDIM * BDIM);
    wconv_kernel<<<(DFF * BDIM + 255) / 256, 256>>>(W1, wc + WC_W1, DFF * BDIM);
    wconv_kernel<<<(DFF * BDIM + 255) / 256, 256>>>(W2, wc + WC_W2, DFF * BDIM);

    // Convs
    convqk<<<dim3(NTOK / 128, BDIM / 32), 256>>>(src, wt, bq, bk, q, k);
    gemm2<3><<<dim3(NTOK / 128, BDIM / 64), 256>>>(src, wc + WC_WV, bv, nullptr, v, BDIM, BDIM);

    attn_mma<<<dim3(SDIM / 64, NHEADS, BATCH), 128>>>(q, k, v, av);

    gemm2<0><<<dim3(NTOK / 128, BDIM / 64), 256>>>(av, wc + WC_WO, bo, src, t1, BDIM, BDIM);
    ln_kernel<<<NTOK, 256>>>(t1, g1, be1, x1);

    gemm2<1><<<dim3(NTOK / 128, DFF / 64), 256>>>(x1, wc + WC_W1, b1, nullptr, ff, DFF, BDIM);
    gemm2<2><<<dim3(NTOK / 128, BDIM / 64), 256>>>(ff, wc + WC_W2, b2, x1, t1, BDIM, DFF);
    ln_kernel<<<NTOK, 256>>>(t1, g2, be2, out);
}